// round 1
// baseline (speedup 1.0000x reference)
#include <cuda_runtime.h>
#include <cuda_bf16.h>
#include <mma.h>
#include <math.h>
#include <stdint.h>

using namespace nvcuda;

// ---------------- problem constants ----------------
#define MAXN 20000
#define MAXE 100000
#define FDIM 128
#define HC 256          // H*C = 4*64
#define NTYPES 6

// ---------------- scratch (static device memory; no allocs allowed) -------
__device__ __align__(128) float g_xs  [MAXN * FDIM];
__device__ __align__(128) float g_xt  [MAXN * FDIM];
__device__ __align__(128) float g_hs1 [MAXN * HC];
__device__ __align__(128) float g_hd1 [MAXN * HC];
__device__ __align__(128) float g_hs2 [MAXN * HC];
__device__ __align__(128) float g_hd2 [MAXN * HC];
__device__ __align__(128) float g_out1[MAXN * HC];
__device__ __align__(128) float g_out2[MAXN * HC];
__device__ __align__(128) float g_esc [MAXE * 4];
__device__ __align__(128) float g_w   [MAXE * 4];
__device__ __align__(128) float g_emax[MAXN * 4];
__device__ __align__(128) float g_den [MAXN * 4];
__device__ __align__(128) float g_pooled[256];
__device__ __align__(128) float g_agg[8];

// ---------------- small helpers ----------------
__device__ __forceinline__ void red_add_v4(float* p, float a, float b, float c, float d) {
    asm volatile("red.global.add.v4.f32 [%0], {%1, %2, %3, %4};"
                 :: "l"(p), "f"(a), "f"(b), "f"(c), "f"(d) : "memory");
}

__device__ __forceinline__ void atomicMaxFloat(float* addr, float val) {
    int* ia = (int*)addr;
    int old = *ia;
    while (__int_as_float(old) < val) {
        int assumed = old;
        old = atomicCAS(ia, assumed, __float_as_int(val));
        if (old == assumed) break;
    }
}

// ---------------- prep: apply node mask ----------------
__global__ void prep_kernel(const float* __restrict__ x_src,
                            const float* __restrict__ x_tgt5,
                            const float* __restrict__ mask,
                            float* __restrict__ xs, float* __restrict__ xt, int n)
{
    int i = blockIdx.x * blockDim.x + threadIdx.x;
    if (i >= n) return;
    float m = mask[i / FDIM];
    xs[i] = x_src[i]  * m;
    xt[i] = x_tgt5[i] * m;
}

// ---------------- GEMM: C[M,N] = op(A)[M,K] @ B[K,N], tf32 WMMA -----------
#define BM 64
#define BN 64
#define BK 16
#define LDA (BK + 4)
#define LDB (BN + 8)

template<bool RELU>
__global__ void gemm_tf32_kernel(const float* __restrict__ A, const float* __restrict__ B,
                                 float* __restrict__ C, int M, int N, int K)
{
    __shared__ float As[BM * LDA];
    __shared__ float Bs[BK * LDB];

    const int bm = blockIdx.x * BM;
    const int bn = blockIdx.y * BN;
    const int tid = threadIdx.x;
    const int wid = tid >> 5;
    const int warp_m = wid >> 2;   // 0..1 -> 32 rows each
    const int warp_n = wid & 3;    // 0..3 -> 16 cols each

    wmma::fragment<wmma::accumulator, 16, 16, 8, float> acc[2];
    wmma::fill_fragment(acc[0], 0.0f);
    wmma::fill_fragment(acc[1], 0.0f);

    const int a_row = tid >> 2;          // 0..63
    const int a_col = (tid & 3) * 4;     // 0,4,8,12
    const int b_row = tid >> 4;          // 0..15
    const int b_col = (tid & 15) * 4;    // 0..60

    for (int k0 = 0; k0 < K; k0 += BK) {
        int gr = bm + a_row;
        float4 av = make_float4(0.f, 0.f, 0.f, 0.f);
        if (gr < M)
            av = *reinterpret_cast<const float4*>(A + (size_t)gr * K + k0 + a_col);
        if (RELU) {
            av.x = fmaxf(av.x, 0.f); av.y = fmaxf(av.y, 0.f);
            av.z = fmaxf(av.z, 0.f); av.w = fmaxf(av.w, 0.f);
        }
        *reinterpret_cast<float4*>(&As[a_row * LDA + a_col]) = av;

        float4 bv = *reinterpret_cast<const float4*>(B + (size_t)(k0 + b_row) * N + bn + b_col);
        *reinterpret_cast<float4*>(&Bs[b_row * LDB + b_col]) = bv;
        __syncthreads();

        #pragma unroll
        for (int kk = 0; kk < BK; kk += 8) {
            wmma::fragment<wmma::matrix_b, 16, 16, 8, wmma::precision::tf32, wmma::row_major> bf;
            wmma::load_matrix_sync(bf, &Bs[kk * LDB + warp_n * 16], LDB);
            #pragma unroll
            for (int i = 0; i < bf.num_elements; i++) bf.x[i] = wmma::__float_to_tf32(bf.x[i]);
            #pragma unroll
            for (int mi = 0; mi < 2; mi++) {
                wmma::fragment<wmma::matrix_a, 16, 16, 8, wmma::precision::tf32, wmma::row_major> af;
                wmma::load_matrix_sync(af, &As[(warp_m * 32 + mi * 16) * LDA + kk], LDA);
                #pragma unroll
                for (int i = 0; i < af.num_elements; i++) af.x[i] = wmma::__float_to_tf32(af.x[i]);
                wmma::mma_sync(acc[mi], af, bf, acc[mi]);
            }
        }
        __syncthreads();
    }

    #pragma unroll
    for (int mi = 0; mi < 2; mi++) {
        int r0 = bm + warp_m * 32 + mi * 16;
        if (r0 < M)
            wmma::store_matrix_sync(C + (size_t)r0 * N + bn + warp_n * 16, acc[mi],
                                    N, wmma::mem_row_major);
    }
}

// ---------------- init per layer ----------------
__global__ void init_kernel(float* __restrict__ emax, float* __restrict__ den,
                            float* __restrict__ out, float* __restrict__ pooled, int nt)
{
    int i = blockIdx.x * blockDim.x + threadIdx.x;
    if (i < nt * 4) { emax[i] = -INFINITY; den[i] = 0.f; }
    if (pooled != nullptr && i < 256) pooled[i] = 0.f;
    if (i < nt * HC) out[i] = 0.f;
}

// ---------------- edge pass 1: scores + segment max ----------------
// one warp per edge; lane handles float4 #lane and #(lane+32) of 64
__global__ void edge_score_kernel(const float* __restrict__ hs, const float* __restrict__ hd,
                                  const float* __restrict__ a,
                                  const int* __restrict__ src, const int* __restrict__ dst,
                                  float* __restrict__ esc, float* __restrict__ emax, int E)
{
    int e = (blockIdx.x * blockDim.x + threadIdx.x) >> 5;
    if (e >= E) return;
    int lane = threadIdx.x & 31;
    int s = src[e], d = dst[e];
    const float4* hs4 = reinterpret_cast<const float4*>(hs) + (size_t)s * 64;
    const float4* hd4 = reinterpret_cast<const float4*>(hd) + (size_t)d * 64;
    const float4* a4  = reinterpret_cast<const float4*>(a);

    float p[2];
    #pragma unroll
    for (int half = 0; half < 2; half++) {
        int f = lane + half * 32;
        float4 u = hs4[f], v = hd4[f], av = a4[f];
        float zx = u.x + v.x, zy = u.y + v.y, zz = u.z + v.z, zw = u.w + v.w;
        zx = zx > 0.f ? zx : 0.2f * zx;
        zy = zy > 0.f ? zy : 0.2f * zy;
        zz = zz > 0.f ? zz : 0.2f * zz;
        zw = zw > 0.f ? zw : 0.2f * zw;
        p[half] = zx * av.x + zy * av.y + zz * av.z + zw * av.w;
    }
    #pragma unroll
    for (int off = 8; off > 0; off >>= 1) {
        p[0] += __shfl_down_sync(0xffffffffu, p[0], off, 16);
        p[1] += __shfl_down_sync(0xffffffffu, p[1], off, 16);
    }
    if ((lane & 15) == 0) {
        int h = lane >> 4;  // 0 or 1; second half covers heads h+2
        esc[(size_t)e * 4 + h]     = p[0];
        esc[(size_t)e * 4 + h + 2] = p[1];
        atomicMaxFloat(&emax[(size_t)d * 4 + h],     p[0]);
        atomicMaxFloat(&emax[(size_t)d * 4 + h + 2], p[1]);
    }
}

// ---------------- edge pass 2: exp weights + denominator ----------------
__global__ void edge_softmax_kernel(const float* __restrict__ esc, const float* __restrict__ emax,
                                    const float* __restrict__ emask, const int* __restrict__ dst,
                                    float* __restrict__ w, float* __restrict__ den, int E)
{
    int e = blockIdx.x * blockDim.x + threadIdx.x;
    if (e >= E) return;
    int d = dst[e];
    float4 ev = *reinterpret_cast<const float4*>(esc + (size_t)e * 4);
    float4 mv = *reinterpret_cast<const float4*>(emax + (size_t)d * 4);
    float m = emask[e];
    float4 wv;
    wv.x = expf(ev.x - mv.x) * m;
    wv.y = expf(ev.y - mv.y) * m;
    wv.z = expf(ev.z - mv.z) * m;
    wv.w = expf(ev.w - mv.w) * m;
    *reinterpret_cast<float4*>(w + (size_t)e * 4) = wv;
    red_add_v4(den + (size_t)d * 4, wv.x, wv.y, wv.z, wv.w);
}

// ---------------- edge pass 3: weighted scatter ----------------
__global__ void edge_aggregate_kernel(const float* __restrict__ w, const float* __restrict__ den,
                                      const float* __restrict__ hs,
                                      const int* __restrict__ src, const int* __restrict__ dst,
                                      float* __restrict__ out, int E)
{
    int e = (blockIdx.x * blockDim.x + threadIdx.x) >> 5;
    if (e >= E) return;
    int lane = threadIdx.x & 31;
    int s = src[e], d = dst[e];
    const float4* hs4 = reinterpret_cast<const float4*>(hs) + (size_t)s * 64;

    #pragma unroll
    for (int half = 0; half < 2; half++) {
        int f = lane + half * 32;
        int h = f >> 4;
        float alpha = w[(size_t)e * 4 + h] / (den[(size_t)d * 4 + h] + 1e-16f);
        float4 v = hs4[f];
        red_add_v4(out + (size_t)d * HC + f * 4,
                   v.x * alpha, v.y * alpha, v.z * alpha, v.w * alpha);
    }
}

// ---------------- pooling, edge-attr mean, classifier ----------------
__global__ void pool_kernel(const float* __restrict__ out2, float* __restrict__ pooled, int nt)
{
    int t = threadIdx.x;  // 256 threads
    float acc = 0.f;
    for (int r = blockIdx.x; r < nt; r += gridDim.x)
        acc += out2[(size_t)r * HC + t];
    atomicAdd(&pooled[t], acc);
}

__global__ void edgeattr_kernel(const float* __restrict__ ea, float* __restrict__ agg, int E)
{
    int t = blockIdx.x;  // one block per edge type
    const float* p = ea + (size_t)t * E;
    float acc = 0.f;
    for (int i = threadIdx.x; i < E; i += blockDim.x) acc += p[i];
    __shared__ float sm[256];
    sm[threadIdx.x] = acc;
    __syncthreads();
    for (int s = 128; s > 0; s >>= 1) {
        if (threadIdx.x < s) sm[threadIdx.x] += sm[threadIdx.x + s];
        __syncthreads();
    }
    if (threadIdx.x == 0) agg[t] = sm[0];
}

__global__ void final_kernel(const float* __restrict__ pooled, const float* __restrict__ agg,
                             const float* __restrict__ Wc, const float* __restrict__ bc,
                             float* __restrict__ out, int nt, int E)
{
    int t = threadIdx.x;  // 256 threads
    __shared__ float sm[256];
    sm[t] = pooled[t] * (1.0f / (float)nt) * Wc[t];
    __syncthreads();
    for (int s = 128; s > 0; s >>= 1) {
        if (t < s) sm[t] += sm[t + s];
        __syncthreads();
    }
    if (t == 0) {
        float v = sm[0] + bc[0];
        #pragma unroll
        for (int i = 0; i < NTYPES; i++)
            v += (agg[i] / (float)E) * Wc[256 + i];
        out[0] = 1.0f / (1.0f + expf(-v));
    }
}

// ---------------- host launch ----------------
extern "C" void kernel_launch(void* const* d_in, const int* in_sizes, int n_in,
                              void* d_out, int out_size)
{
    const float* x_src     = (const float*)d_in[0];
    const float* x_tgt     = (const float*)d_in[1];
    const float* edge_attr = (const float*)d_in[2];
    const float* node_mask = (const float*)d_in[3];
    const float* edge_mask = (const float*)d_in[4];
    const int*   edge_idx  = (const int*)  d_in[5];
    const float* W1s = (const float*)d_in[6];
    const float* W1d = (const float*)d_in[7];
    const float* a1  = (const float*)d_in[8];
    const float* W2s = (const float*)d_in[9];
    const float* W2d = (const float*)d_in[10];
    const float* a2  = (const float*)d_in[11];
    const float* Wc  = (const float*)d_in[12];
    const float* bc  = (const float*)d_in[13];
    float* out = (float*)d_out;

    const int Ns = in_sizes[3];
    const int E  = in_sizes[4];
    const int Nt = in_sizes[1] / (NTYPES * FDIM);
    const int t  = NTYPES - 1;   // only the last edge type affects the output

    float *xs, *xt, *hs1, *hd1, *hs2, *hd2, *o1, *o2, *esc, *w, *emax, *den, *pooled, *agg;
    cudaGetSymbolAddress((void**)&xs,  g_xs);
    cudaGetSymbolAddress((void**)&xt,  g_xt);
    cudaGetSymbolAddress((void**)&hs1, g_hs1);
    cudaGetSymbolAddress((void**)&hd1, g_hd1);
    cudaGetSymbolAddress((void**)&hs2, g_hs2);
    cudaGetSymbolAddress((void**)&hd2, g_hd2);
    cudaGetSymbolAddress((void**)&o1,  g_out1);
    cudaGetSymbolAddress((void**)&o2,  g_out2);
    cudaGetSymbolAddress((void**)&esc, g_esc);
    cudaGetSymbolAddress((void**)&w,   g_w);
    cudaGetSymbolAddress((void**)&emax,g_emax);
    cudaGetSymbolAddress((void**)&den, g_den);
    cudaGetSymbolAddress((void**)&pooled, g_pooled);
    cudaGetSymbolAddress((void**)&agg, g_agg);

    const float* x_tgt5 = x_tgt + (size_t)t * Nt * FDIM;
    const float* W1s_t = W1s + (size_t)t * FDIM * HC;
    const float* W1d_t = W1d + (size_t)t * FDIM * HC;
    const float* W2s_t = W2s + (size_t)t * FDIM * HC;
    const float* W2d_t = W2d + (size_t)t * HC * HC;
    const float* a1_t = a1 + (size_t)t * HC;
    const float* a2_t = a2 + (size_t)t * HC;
    const int* src = edge_idx + (size_t)t * 2 * E;
    const int* dst = src + E;

    // 1. node mask
    {
        int n = Ns * FDIM;
        prep_kernel<<<(n + 255) / 256, 256>>>(x_src, x_tgt5, node_mask, xs, xt, n);
    }

    dim3 ggrid((Ns + BM - 1) / BM, HC / BN);
    // 2-4. input GEMMs (tf32)
    gemm_tf32_kernel<false><<<ggrid, 256>>>(xs, W1s_t, hs1, Ns, HC, FDIM);
    gemm_tf32_kernel<false><<<ggrid, 256>>>(xt, W1d_t, hd1, Nt, HC, FDIM);
    gemm_tf32_kernel<false><<<ggrid, 256>>>(xs, W2s_t, hs2, Ns, HC, FDIM);

    int eblk_w = (E * 32 + 255) / 256;   // warp-per-edge kernels
    int eblk_t = (E + 255) / 256;        // thread-per-edge kernels
    int iblk   = (Nt * HC + 255) / 256;

    // ---- layer 1 attention ----
    init_kernel<<<iblk, 256>>>(emax, den, o1, nullptr, Nt);
    edge_score_kernel<<<eblk_w, 256>>>(hs1, hd1, a1_t, src, dst, esc, emax, E);
    edge_softmax_kernel<<<eblk_t, 256>>>(esc, emax, edge_mask, dst, w, den, E);
    edge_aggregate_kernel<<<eblk_w, 256>>>(w, den, hs1, src, dst, o1, E);

    // ---- layer 2 ----
    // hd2 = relu(o1) @ W2_dst   (relu folded into A-load)
    gemm_tf32_kernel<true><<<ggrid, 256>>>(o1, W2d_t, hd2, Nt, HC, HC);

    init_kernel<<<iblk, 256>>>(emax, den, o2, pooled, Nt);
    edge_score_kernel<<<eblk_w, 256>>>(hs2, hd2, a2_t, src, dst, esc, emax, E);
    edge_softmax_kernel<<<eblk_t, 256>>>(esc, emax, edge_mask, dst, w, den, E);
    edge_aggregate_kernel<<<eblk_w, 256>>>(w, den, hs2, src, dst, o2, E);

    // ---- readout ----
    pool_kernel<<<256, 256>>>(o2, pooled, Nt);
    edgeattr_kernel<<<NTYPES, 256>>>(edge_attr, agg, E);
    final_kernel<<<1, 256>>>(pooled, agg, Wc, bc, out, Nt, E);
}

// round 2
// speedup vs baseline: 1.1977x; 1.1977x over previous
#include <cuda_runtime.h>
#include <cuda_bf16.h>
#include <mma.h>
#include <math.h>
#include <stdint.h>

using namespace nvcuda;

// ---------------- problem constants ----------------
#define MAXN 20000
#define MAXE 100000
#define FDIM 128
#define HC 256          // H*C = 4*64
#define NTYPES 6

// ---------------- scratch (static device memory) ----------------
__device__ __align__(128) float g_hs1 [MAXN * HC];
__device__ __align__(128) float g_hs2 [MAXN * HC];
__device__ __align__(128) float g_hd1 [MAXN * HC];
__device__ __align__(128) float g_hd2 [MAXN * HC];
__device__ __align__(128) float g_o1  [MAXN * HC];
__device__ __align__(128) float g_o2  [MAXN * HC];
__device__ __align__(128) float g_den1[MAXN * 4];
__device__ __align__(128) float g_den2[MAXN * 4];
__device__ __align__(128) float g_pooled[256];
__device__ __align__(128) float g_agg[8];

// ---------------- helpers ----------------
__device__ __forceinline__ void red_add_v4(float* p, float a, float b, float c, float d) {
    asm volatile("red.global.add.v4.f32 [%0], {%1, %2, %3, %4};"
                 :: "l"(p), "f"(a), "f"(b), "f"(c), "f"(d) : "memory");
}
__device__ __forceinline__ void red_add_f32(float* p, float a) {
    asm volatile("red.global.add.f32 [%0], %1;" :: "l"(p), "f"(a) : "memory");
}

// ---------------- GEMM: C = xform(A)[M,K] @ B[K,N], tf32 WMMA ----------------
// BM=128 BN=128 BK=16, 256 threads, 8 warps in 2x4, warp tile 64x32.
// MODE 0: plain  1: A[r,k]*=mask[r]  2: A[r,k] = relu(A[r,k]*inv[r*4 + (k>>6)])
// If B2 != nullptr, global column >= 256 selects (B2, C2) with col-256.
#define BM 128
#define BN 128
#define BK 16
#define LDA (BK + 4)
#define LDB (BN + 8)

template<int MODE>
__global__ __launch_bounds__(256, 2)
void gemm_tf32_kernel(const float* __restrict__ A,
                      const float* __restrict__ B1, const float* __restrict__ B2,
                      float* __restrict__ C1, float* __restrict__ C2,
                      const float* __restrict__ xf,
                      int M, int K)
{
    __shared__ float As[BM * LDA];
    __shared__ float Bs[BK * LDB];

    const int bm = blockIdx.x * BM;
    const int bnG = blockIdx.y * BN;             // global output column
    const bool second = (bnG >= HC);
    const float* Bp = second ? B2 : B1;
    float*       Cp = second ? C2 : C1;
    const int bn = second ? (bnG - HC) : bnG;    // column within selected 256-wide output

    const int tid = threadIdx.x;
    const int wid = tid >> 5;
    const int warp_m = wid >> 2;    // 0..1  -> 64 rows
    const int warp_n = wid & 3;     // 0..3  -> 32 cols

    wmma::fragment<wmma::accumulator, 16, 16, 8, float> acc[4][2];
    #pragma unroll
    for (int i = 0; i < 4; i++) {
        wmma::fill_fragment(acc[i][0], 0.0f);
        wmma::fill_fragment(acc[i][1], 0.0f);
    }

    for (int k0 = 0; k0 < K; k0 += BK) {
        // A: 128x16 = 512 float4, 2 per thread
        #pragma unroll
        for (int i = 0; i < 2; i++) {
            int idx = tid + i * 256;
            int row = idx >> 2;
            int c4  = (idx & 3) * 4;
            int gr = bm + row;
            float4 av = make_float4(0.f, 0.f, 0.f, 0.f);
            if (gr < M) {
                av = *reinterpret_cast<const float4*>(A + (size_t)gr * K + k0 + c4);
                if (MODE == 1) {
                    float m = __ldg(xf + gr);
                    av.x *= m; av.y *= m; av.z *= m; av.w *= m;
                } else if (MODE == 2) {
                    float inv = __ldg(xf + gr * 4 + ((k0 + c4) >> 6));
                    av.x = fmaxf(av.x * inv, 0.f); av.y = fmaxf(av.y * inv, 0.f);
                    av.z = fmaxf(av.z * inv, 0.f); av.w = fmaxf(av.w * inv, 0.f);
                }
            }
            av.x = wmma::__float_to_tf32(av.x); av.y = wmma::__float_to_tf32(av.y);
            av.z = wmma::__float_to_tf32(av.z); av.w = wmma::__float_to_tf32(av.w);
            *reinterpret_cast<float4*>(&As[row * LDA + c4]) = av;
        }
        // B: 16x128 = 512 float4, 2 per thread
        #pragma unroll
        for (int i = 0; i < 2; i++) {
            int idx = tid + i * 256;
            int row = idx >> 5;
            int c4  = (idx & 31) * 4;
            float4 bv = *reinterpret_cast<const float4*>(Bp + (size_t)(k0 + row) * HC + bn + c4);
            bv.x = wmma::__float_to_tf32(bv.x); bv.y = wmma::__float_to_tf32(bv.y);
            bv.z = wmma::__float_to_tf32(bv.z); bv.w = wmma::__float_to_tf32(bv.w);
            *reinterpret_cast<float4*>(&Bs[row * LDB + c4]) = bv;
        }
        __syncthreads();

        #pragma unroll
        for (int kk = 0; kk < BK; kk += 8) {
            wmma::fragment<wmma::matrix_b, 16, 16, 8, wmma::precision::tf32, wmma::row_major> bf[2];
            wmma::load_matrix_sync(bf[0], &Bs[kk * LDB + warp_n * 32],      LDB);
            wmma::load_matrix_sync(bf[1], &Bs[kk * LDB + warp_n * 32 + 16], LDB);
            #pragma unroll
            for (int mi = 0; mi < 4; mi++) {
                wmma::fragment<wmma::matrix_a, 16, 16, 8, wmma::precision::tf32, wmma::row_major> af;
                wmma::load_matrix_sync(af, &As[(warp_m * 64 + mi * 16) * LDA + kk], LDA);
                wmma::mma_sync(acc[mi][0], af, bf[0], acc[mi][0]);
                wmma::mma_sync(acc[mi][1], af, bf[1], acc[mi][1]);
            }
        }
        __syncthreads();
    }

    #pragma unroll
    for (int mi = 0; mi < 4; mi++) {
        int r0 = bm + warp_m * 64 + mi * 16;
        if (r0 < M) {   // M divisible by 16 -> fragment-granular guard is exact
            wmma::store_matrix_sync(Cp + (size_t)r0 * HC + bn + warp_n * 32,      acc[mi][0], HC, wmma::mem_row_major);
            wmma::store_matrix_sync(Cp + (size_t)r0 * HC + bn + warp_n * 32 + 16, acc[mi][1], HC, wmma::mem_row_major);
        }
    }
}

// ---------------- fused edge layer: score + exp + scatter ----------------
// One warp per edge. e_h = a_h . leaky_relu(hs[src]+hd[dst]); w = exp(e)*mask;
// out[dst] += w*hs[src]; den[dst,h] += w_h.   (No max-subtraction: exp(e) safe
// here and the normalization e-emax cancels in alpha.)
__global__ __launch_bounds__(256)
void edge_fused_kernel(const float* __restrict__ hs, const float* __restrict__ hd,
                       const float* __restrict__ a,  const float* __restrict__ emask,
                       const int* __restrict__ src,  const int* __restrict__ dst,
                       float* __restrict__ outp, float* __restrict__ den, int E)
{
    int e = (blockIdx.x * blockDim.x + threadIdx.x) >> 5;
    if (e >= E) return;
    int lane = threadIdx.x & 31;
    int s = src[e], d = dst[e];
    const float4* u4 = reinterpret_cast<const float4*>(hs) + (size_t)s * 64;
    const float4* v4 = reinterpret_cast<const float4*>(hd) + (size_t)d * 64;
    const float4* a4 = reinterpret_cast<const float4*>(a);

    float4 u0, u1;
    float p[2];
    #pragma unroll
    for (int half = 0; half < 2; half++) {
        int f = lane + half * 32;
        float4 u = u4[f], v = v4[f], av = a4[f];
        if (half == 0) u0 = u; else u1 = u;
        float zx = u.x + v.x, zy = u.y + v.y, zz = u.z + v.z, zw = u.w + v.w;
        zx = zx > 0.f ? zx : 0.2f * zx;
        zy = zy > 0.f ? zy : 0.2f * zy;
        zz = zz > 0.f ? zz : 0.2f * zz;
        zw = zw > 0.f ? zw : 0.2f * zw;
        p[half] = zx * av.x + zy * av.y + zz * av.z + zw * av.w;
    }
    // butterfly sum within 16-lane groups: lanes 0-15 get head h (h=0 or 2),
    // lanes 16-31 get head h+1.
    #pragma unroll
    for (int off = 8; off > 0; off >>= 1) {
        p[0] += __shfl_xor_sync(0xffffffffu, p[0], off, 16);
        p[1] += __shfl_xor_sync(0xffffffffu, p[1], off, 16);
    }
    float m = __ldg(emask + e);
    float w0 = __expf(p[0]) * m;   // head (lane<16 ? 0 : 1)
    float w1 = __expf(p[1]) * m;   // head (lane<16 ? 2 : 3)

    float* base = outp + (size_t)d * HC;
    red_add_v4(base + lane * 4,        u0.x * w0, u0.y * w0, u0.z * w0, u0.w * w0);
    red_add_v4(base + (lane + 32) * 4, u1.x * w1, u1.y * w1, u1.z * w1, u1.w * w1);
    if (lane == 0)  { red_add_f32(den + (size_t)d * 4 + 0, w0); red_add_f32(den + (size_t)d * 4 + 2, w1); }
    if (lane == 16) { red_add_f32(den + (size_t)d * 4 + 1, w0); red_add_f32(den + (size_t)d * 4 + 3, w1); }
}

// ---------------- tiny: den -> 1/(den+eps) ----------------
__global__ void invden_kernel(float* __restrict__ den, int n) {
    int i = blockIdx.x * blockDim.x + threadIdx.x;
    if (i < n) den[i] = __fdividef(1.0f, den[i] + 1e-16f);
}

// ---------------- pooling (normalized), edge-attr mean, classifier ----------
__global__ void pool_kernel(const float* __restrict__ o2, const float* __restrict__ inv,
                            float* __restrict__ pooled, int nt)
{
    int c = threadIdx.x;  // 256
    int h = c >> 6;
    float acc = 0.f;
    for (int r = blockIdx.x; r < nt; r += gridDim.x)
        acc += o2[(size_t)r * HC + c] * __ldg(inv + (size_t)r * 4 + h);
    atomicAdd(&pooled[c], acc);
}

__global__ void edgeattr_kernel(const float* __restrict__ ea, float* __restrict__ agg, int E)
{
    int t = blockIdx.x;
    const float* p = ea + (size_t)t * E;
    float acc = 0.f;
    for (int i = threadIdx.x; i < E; i += blockDim.x) acc += p[i];
    __shared__ float sm[256];
    sm[threadIdx.x] = acc;
    __syncthreads();
    for (int s = 128; s > 0; s >>= 1) {
        if (threadIdx.x < s) sm[threadIdx.x] += sm[threadIdx.x + s];
        __syncthreads();
    }
    if (threadIdx.x == 0) agg[t] = sm[0];
}

__global__ void final_kernel(const float* __restrict__ pooled, const float* __restrict__ agg,
                             const float* __restrict__ Wc, const float* __restrict__ bc,
                             float* __restrict__ out, int nt, int E)
{
    int t = threadIdx.x;  // 256
    __shared__ float sm[256];
    sm[t] = pooled[t] * (1.0f / (float)nt) * Wc[t];
    __syncthreads();
    for (int s = 128; s > 0; s >>= 1) {
        if (t < s) sm[t] += sm[t + s];
        __syncthreads();
    }
    if (t == 0) {
        float v = sm[0] + bc[0];
        #pragma unroll
        for (int i = 0; i < NTYPES; i++)
            v += (agg[i] / (float)E) * Wc[256 + i];
        out[0] = 1.0f / (1.0f + expf(-v));
    }
}

// ---------------- host launch ----------------
extern "C" void kernel_launch(void* const* d_in, const int* in_sizes, int n_in,
                              void* d_out, int out_size)
{
    const float* x_src     = (const float*)d_in[0];
    const float* x_tgt     = (const float*)d_in[1];
    const float* edge_attr = (const float*)d_in[2];
    const float* node_mask = (const float*)d_in[3];
    const float* edge_mask = (const float*)d_in[4];
    const int*   edge_idx  = (const int*)  d_in[5];
    const float* W1s = (const float*)d_in[6];
    const float* W1d = (const float*)d_in[7];
    const float* a1  = (const float*)d_in[8];
    const float* W2s = (const float*)d_in[9];
    const float* W2d = (const float*)d_in[10];
    const float* a2  = (const float*)d_in[11];
    const float* Wc  = (const float*)d_in[12];
    const float* bc  = (const float*)d_in[13];
    float* out = (float*)d_out;

    const int Ns = in_sizes[3];
    const int E  = in_sizes[4];
    const int Nt = in_sizes[1] / (NTYPES * FDIM);
    const int t  = NTYPES - 1;   // only the last edge type affects the output

    float *hs1, *hs2, *hd1, *hd2, *o1, *o2, *den1, *den2, *pooled, *agg;
    cudaGetSymbolAddress((void**)&hs1, g_hs1);
    cudaGetSymbolAddress((void**)&hs2, g_hs2);
    cudaGetSymbolAddress((void**)&hd1, g_hd1);
    cudaGetSymbolAddress((void**)&hd2, g_hd2);
    cudaGetSymbolAddress((void**)&o1,  g_o1);
    cudaGetSymbolAddress((void**)&o2,  g_o2);
    cudaGetSymbolAddress((void**)&den1, g_den1);
    cudaGetSymbolAddress((void**)&den2, g_den2);
    cudaGetSymbolAddress((void**)&pooled, g_pooled);
    cudaGetSymbolAddress((void**)&agg, g_agg);

    const float* x_tgt5 = x_tgt + (size_t)t * Nt * FDIM;
    const float* W1s_t = W1s + (size_t)t * FDIM * HC;
    const float* W1d_t = W1d + (size_t)t * FDIM * HC;
    const float* W2s_t = W2s + (size_t)t * FDIM * HC;
    const float* W2d_t = W2d + (size_t)t * HC * HC;
    const float* a1_t = a1 + (size_t)t * HC;
    const float* a2_t = a2 + (size_t)t * HC;
    const int* src = edge_idx + (size_t)t * 2 * E;
    const int* dst = src + E;

    // zero accumulators
    cudaMemsetAsync(o1,   0, (size_t)Nt * HC * sizeof(float));
    cudaMemsetAsync(o2,   0, (size_t)Nt * HC * sizeof(float));
    cudaMemsetAsync(den1, 0, (size_t)Nt * 4 * sizeof(float));
    cudaMemsetAsync(den2, 0, (size_t)Nt * 4 * sizeof(float));
    cudaMemsetAsync(pooled, 0, 256 * sizeof(float));

    const int gmx = (Ns + BM - 1) / BM;
    // hs1|hs2 = (xs*mask) @ [W1s | W2s]  -- one pass over A, N=512
    gemm_tf32_kernel<1><<<dim3(gmx, 4), 256>>>(x_src, W1s_t, W2s_t, hs1, hs2, node_mask, Ns, FDIM);
    // hd1 = (xt*mask) @ W1d
    gemm_tf32_kernel<1><<<dim3(gmx, 2), 256>>>(x_tgt5, W1d_t, nullptr, hd1, nullptr, node_mask, Nt, FDIM);

    const int eblk = (E * 32 + 255) / 256;

    // layer 1 (fused attention)
    edge_fused_kernel<<<eblk, 256>>>(hs1, hd1, a1_t, edge_mask, src, dst, o1, den1, E);
    invden_kernel<<<(Nt * 4 + 255) / 256, 256>>>(den1, Nt * 4);

    // hd2 = relu(o1 * invden1) @ W2d   (normalize+relu folded into A-load)
    gemm_tf32_kernel<2><<<dim3(gmx, 2), 256>>>(o1, W2d_t, nullptr, hd2, nullptr, den1, Nt, HC);

    // layer 2
    edge_fused_kernel<<<eblk, 256>>>(hs2, hd2, a2_t, edge_mask, src, dst, o2, den2, E);
    invden_kernel<<<(Nt * 4 + 255) / 256, 256>>>(den2, Nt * 4);

    // readout
    pool_kernel<<<256, 256>>>(o2, den2, pooled, Nt);
    edgeattr_kernel<<<NTYPES, 256>>>(edge_attr, agg, E);
    final_kernel<<<1, 256>>>(pooled, agg, Wc, bc, out, Nt, E);
}

// round 4
// speedup vs baseline: 1.2261x; 1.0237x over previous
#include <cuda_runtime.h>
#include <cuda_bf16.h>
#include <mma.h>
#include <math.h>
#include <stdint.h>

using namespace nvcuda;

// ---------------- problem constants ----------------
#define MAXN 20000
#define MAXE 100000
#define FDIM 128
#define HC 256          // H*C = 4*64
#define NTYPES 6

// ---------------- scratch (static device memory) ----------------
__device__ __align__(128) float g_hs1 [MAXN * HC];
__device__ __align__(128) float g_hs2 [MAXN * HC];
__device__ __align__(128) float g_hd1 [MAXN * HC];
__device__ __align__(128) float g_hd2 [MAXN * HC];
__device__ __align__(128) float g_h1  [MAXN * HC];   // normalized+relu layer-1 out
__device__ __align__(128) int   g_cnt   [MAXN];
__device__ __align__(128) int   g_offs  [MAXN + 1];
__device__ __align__(128) int   g_cursor[MAXN];
__device__ __align__(128) int   g_csrs  [MAXE];
__device__ __align__(128) float g_csrm  [MAXE];
__device__ __align__(128) float g_pooled[256];
__device__ __align__(128) float g_agg[8];

// ---------------- helpers ----------------
__device__ __forceinline__ void red_add_v4(float* p, float a, float b, float c, float d) {
    asm volatile("red.global.add.v4.f32 [%0], {%1, %2, %3, %4};"
                 :: "l"(p), "f"(a), "f"(b), "f"(c), "f"(d) : "memory");
}

// ---------------- GEMM: C = xform(A)[M,K] @ B[K,N], tf32 WMMA ----------------
// BM=128 BN=128 BK=16, 256 threads, 8 warps in 2x4, warp tile 64x32.
// MODE 0: plain   MODE 1: A[r,k] *= mask[r]
// If B2 != nullptr, global column >= 256 selects (B2, C2) with col-256.
#define BM 128
#define BN 128
#define BK 16
#define LDA (BK + 4)
#define LDB (BN + 8)

template<int MODE>
__global__ __launch_bounds__(256, 2)
void gemm_tf32_kernel(const float* __restrict__ A,
                      const float* __restrict__ B1, const float* __restrict__ B2,
                      float* __restrict__ C1, float* __restrict__ C2,
                      const float* __restrict__ xf,
                      int M, int K)
{
    __shared__ float As[BM * LDA];
    __shared__ float Bs[BK * LDB];

    const int bm = blockIdx.x * BM;
    const int bnG = blockIdx.y * BN;
    const bool second = (bnG >= HC);
    const float* Bp = second ? B2 : B1;
    float*       Cp = second ? C2 : C1;
    const int bn = second ? (bnG - HC) : bnG;

    const int tid = threadIdx.x;
    const int wid = tid >> 5;
    const int warp_m = wid >> 2;    // 0..1 -> 64 rows
    const int warp_n = wid & 3;     // 0..3 -> 32 cols

    wmma::fragment<wmma::accumulator, 16, 16, 8, float> acc[4][2];
    #pragma unroll
    for (int i = 0; i < 4; i++) {
        wmma::fill_fragment(acc[i][0], 0.0f);
        wmma::fill_fragment(acc[i][1], 0.0f);
    }

    for (int k0 = 0; k0 < K; k0 += BK) {
        #pragma unroll
        for (int i = 0; i < 2; i++) {
            int idx = tid + i * 256;
            int row = idx >> 2;
            int c4  = (idx & 3) * 4;
            int gr = bm + row;
            float4 av = make_float4(0.f, 0.f, 0.f, 0.f);
            if (gr < M) {
                av = *reinterpret_cast<const float4*>(A + (size_t)gr * K + k0 + c4);
                if (MODE == 1) {
                    float m = __ldg(xf + gr);
                    av.x *= m; av.y *= m; av.z *= m; av.w *= m;
                }
            }
            av.x = wmma::__float_to_tf32(av.x); av.y = wmma::__float_to_tf32(av.y);
            av.z = wmma::__float_to_tf32(av.z); av.w = wmma::__float_to_tf32(av.w);
            *reinterpret_cast<float4*>(&As[row * LDA + c4]) = av;
        }
        #pragma unroll
        for (int i = 0; i < 2; i++) {
            int idx = tid + i * 256;
            int row = idx >> 5;
            int c4  = (idx & 31) * 4;
            float4 bv = *reinterpret_cast<const float4*>(Bp + (size_t)(k0 + row) * HC + bn + c4);
            bv.x = wmma::__float_to_tf32(bv.x); bv.y = wmma::__float_to_tf32(bv.y);
            bv.z = wmma::__float_to_tf32(bv.z); bv.w = wmma::__float_to_tf32(bv.w);
            *reinterpret_cast<float4*>(&Bs[row * LDB + c4]) = bv;
        }
        __syncthreads();

        #pragma unroll
        for (int kk = 0; kk < BK; kk += 8) {
            wmma::fragment<wmma::matrix_b, 16, 16, 8, wmma::precision::tf32, wmma::row_major> bf[2];
            wmma::load_matrix_sync(bf[0], &Bs[kk * LDB + warp_n * 32],      LDB);
            wmma::load_matrix_sync(bf[1], &Bs[kk * LDB + warp_n * 32 + 16], LDB);
            #pragma unroll
            for (int mi = 0; mi < 4; mi++) {
                wmma::fragment<wmma::matrix_a, 16, 16, 8, wmma::precision::tf32, wmma::row_major> af;
                wmma::load_matrix_sync(af, &As[(warp_m * 64 + mi * 16) * LDA + kk], LDA);
                wmma::mma_sync(acc[mi][0], af, bf[0], acc[mi][0]);
                wmma::mma_sync(acc[mi][1], af, bf[1], acc[mi][1]);
            }
        }
        __syncthreads();
    }

    #pragma unroll
    for (int mi = 0; mi < 4; mi++) {
        int r0 = bm + warp_m * 64 + mi * 16;
        if (r0 < M) {
            wmma::store_matrix_sync(Cp + (size_t)r0 * HC + bn + warp_n * 32,      acc[mi][0], HC, wmma::mem_row_major);
            wmma::store_matrix_sync(Cp + (size_t)r0 * HC + bn + warp_n * 32 + 16, acc[mi][1], HC, wmma::mem_row_major);
        }
    }
}

// ---------------- CSR build ----------------
__global__ void hist_kernel(const int* __restrict__ dst, int* __restrict__ cnt, int E)
{
    int i = blockIdx.x * blockDim.x + threadIdx.x;
    if (i < E) atomicAdd(&cnt[dst[i]], 1);
}

// single-block exclusive scan over n counts -> offs[0..n], cursor copy
__global__ void scan_kernel(const int* __restrict__ cnt, int* __restrict__ offs,
                            int* __restrict__ cursor, int n)
{
    __shared__ int sm[1024];
    __shared__ int carry_s;
    int tid = threadIdx.x;
    if (tid == 0) carry_s = 0;
    __syncthreads();
    for (int base = 0; base < n; base += 1024) {
        int v = (base + tid < n) ? cnt[base + tid] : 0;
        sm[tid] = v;
        __syncthreads();
        #pragma unroll
        for (int s = 1; s < 1024; s <<= 1) {
            int t = (tid >= s) ? sm[tid - s] : 0;
            __syncthreads();
            sm[tid] += t;
            __syncthreads();
        }
        int excl = carry_s + sm[tid] - v;
        if (base + tid < n) { offs[base + tid] = excl; cursor[base + tid] = excl; }
        __syncthreads();
        if (tid == 1023) carry_s += sm[1023];
        __syncthreads();
    }
    if (tid == 0) offs[n] = carry_s;
}

__global__ void permute_kernel(const int* __restrict__ src, const int* __restrict__ dst,
                               const float* __restrict__ em,
                               int* __restrict__ cursor,
                               int* __restrict__ csrs, float* __restrict__ csrm, int E)
{
    int i = blockIdx.x * blockDim.x + threadIdx.x;
    if (i >= E) return;
    int d = dst[i];
    int p = atomicAdd(&cursor[d], 1);
    csrs[p] = src[i];
    csrm[p] = em[i];
}

// ---------------- aggregation: one warp per destination node ----------------
// e_h = a_h . leaky_relu(hs[s] + hd[d]); w = exp(e)*mask; out = (sum w*hs)/(sum w)
// RELU_OUT: apply relu before writing (layer 1).
// POOL: don't write out; block-reduce node vectors into pooled[256].
// 1-deep software pipeline on the hs[src] gather (MLP=2).
template<bool RELU_OUT, bool POOL>
__global__ __launch_bounds__(256)
void agg_kernel(const float* __restrict__ hs, const float* __restrict__ hd,
                const float* __restrict__ a,
                const int* __restrict__ offs, const int* __restrict__ csrs,
                const float* __restrict__ csrm,
                float* __restrict__ outp, float* __restrict__ pooled, int Nt)
{
    __shared__ float sm[8 * 256];
    const int warp = threadIdx.x >> 5;
    const int lane = threadIdx.x & 31;
    const int d = blockIdx.x * 8 + warp;

    const float4* a4 = reinterpret_cast<const float4*>(a);
    const float4 av0 = a4[lane];
    const float4 av1 = a4[lane + 32];

    float4 acc0 = make_float4(0.f, 0.f, 0.f, 0.f);
    float4 acc1 = make_float4(0.f, 0.f, 0.f, 0.f);

    if (d < Nt) {
        const float4* v4 = reinterpret_cast<const float4*>(hd) + (size_t)d * 64;
        const float4 v0 = v4[lane];
        const float4 v1 = v4[lane + 32];
        float den0 = 0.f, den1 = 0.f;

        const int beg = offs[d], end = offs[d + 1];
        if (beg < end) {
            // prologue: load edge `beg`
            int   s = csrs[beg];
            float m = csrm[beg];
            const float4* u4 = reinterpret_cast<const float4*>(hs) + (size_t)s * 64;
            float4 u0 = u4[lane];
            float4 u1 = u4[lane + 32];

            for (int j = beg; j < end; j++) {
                // prefetch edge j+1 before reducing edge j
                float mn = 0.f;
                float4 u0n, u1n;
                if (j + 1 < end) {
                    int sn = csrs[j + 1];
                    mn = csrm[j + 1];
                    const float4* u4n = reinterpret_cast<const float4*>(hs) + (size_t)sn * 64;
                    u0n = u4n[lane];
                    u1n = u4n[lane + 32];
                }

                float zx, zy, zz, zw, p0, p1;
                zx = u0.x + v0.x; zy = u0.y + v0.y; zz = u0.z + v0.z; zw = u0.w + v0.w;
                zx = zx > 0.f ? zx : 0.2f * zx; zy = zy > 0.f ? zy : 0.2f * zy;
                zz = zz > 0.f ? zz : 0.2f * zz; zw = zw > 0.f ? zw : 0.2f * zw;
                p0 = zx * av0.x + zy * av0.y + zz * av0.z + zw * av0.w;
                zx = u1.x + v1.x; zy = u1.y + v1.y; zz = u1.z + v1.z; zw = u1.w + v1.w;
                zx = zx > 0.f ? zx : 0.2f * zx; zy = zy > 0.f ? zy : 0.2f * zy;
                zz = zz > 0.f ? zz : 0.2f * zz; zw = zw > 0.f ? zw : 0.2f * zw;
                p1 = zx * av1.x + zy * av1.y + zz * av1.z + zw * av1.w;

                #pragma unroll
                for (int off = 8; off > 0; off >>= 1) {
                    p0 += __shfl_xor_sync(0xffffffffu, p0, off, 16);
                    p1 += __shfl_xor_sync(0xffffffffu, p1, off, 16);
                }
                const float w0 = __expf(p0) * m;   // head (lane<16 ? 0 : 1)
                const float w1 = __expf(p1) * m;   // head (lane<16 ? 2 : 3)

                acc0.x += w0 * u0.x; acc0.y += w0 * u0.y; acc0.z += w0 * u0.z; acc0.w += w0 * u0.w;
                acc1.x += w1 * u1.x; acc1.y += w1 * u1.y; acc1.z += w1 * u1.z; acc1.w += w1 * u1.w;
                den0 += w0; den1 += w1;

                u0 = u0n; u1 = u1n; m = mn;
            }
        }

        const float i0 = __fdividef(1.0f, den0 + 1e-16f);
        const float i1 = __fdividef(1.0f, den1 + 1e-16f);
        acc0.x *= i0; acc0.y *= i0; acc0.z *= i0; acc0.w *= i0;
        acc1.x *= i1; acc1.y *= i1; acc1.z *= i1; acc1.w *= i1;
        if (RELU_OUT) {
            acc0.x = fmaxf(acc0.x, 0.f); acc0.y = fmaxf(acc0.y, 0.f);
            acc0.z = fmaxf(acc0.z, 0.f); acc0.w = fmaxf(acc0.w, 0.f);
            acc1.x = fmaxf(acc1.x, 0.f); acc1.y = fmaxf(acc1.y, 0.f);
            acc1.z = fmaxf(acc1.z, 0.f); acc1.w = fmaxf(acc1.w, 0.f);
        }
        if (!POOL) {
            float4* o4 = reinterpret_cast<float4*>(outp) + (size_t)d * 64;
            o4[lane]      = acc0;
            o4[lane + 32] = acc1;
        }
    }

    if (POOL) {
        float4* s4 = reinterpret_cast<float4*>(sm);
        s4[warp * 64 + lane]      = acc0;     // zeros when d >= Nt
        s4[warp * 64 + lane + 32] = acc1;
        __syncthreads();
        if (threadIdx.x < 64) {
            float4 t = make_float4(0.f, 0.f, 0.f, 0.f);
            #pragma unroll
            for (int w = 0; w < 8; w++) {
                float4 q = s4[w * 64 + threadIdx.x];
                t.x += q.x; t.y += q.y; t.z += q.z; t.w += q.w;
            }
            red_add_v4(pooled + threadIdx.x * 4, t.x, t.y, t.z, t.w);
        }
    }
}

// ---------------- edge-attr mean + classifier ----------------
__global__ void edgeattr_kernel(const float* __restrict__ ea, float* __restrict__ agg, int E)
{
    int t = blockIdx.x;
    const float* p = ea + (size_t)t * E;
    float acc = 0.f;
    for (int i = threadIdx.x; i < E; i += blockDim.x) acc += p[i];
    __shared__ float sm[256];
    sm[threadIdx.x] = acc;
    __syncthreads();
    for (int s = 128; s > 0; s >>= 1) {
        if (threadIdx.x < s) sm[threadIdx.x] += sm[threadIdx.x + s];
        __syncthreads();
    }
    if (threadIdx.x == 0) agg[t] = sm[0];
}

__global__ void final_kernel(const float* __restrict__ pooled, const float* __restrict__ agg,
                             const float* __restrict__ Wc, const float* __restrict__ bc,
                             float* __restrict__ out, int nt, int E)
{
    int t = threadIdx.x;  // 256
    __shared__ float sm[256];
    sm[t] = pooled[t] * (1.0f / (float)nt) * Wc[t];
    __syncthreads();
    for (int s = 128; s > 0; s >>= 1) {
        if (t < s) sm[t] += sm[t + s];
        __syncthreads();
    }
    if (t == 0) {
        float v = sm[0] + bc[0];
        #pragma unroll
        for (int i = 0; i < NTYPES; i++)
            v += (agg[i] / (float)E) * Wc[256 + i];
        out[0] = 1.0f / (1.0f + expf(-v));
    }
}

// ---------------- host launch ----------------
extern "C" void kernel_launch(void* const* d_in, const int* in_sizes, int n_in,
                              void* d_out, int out_size)
{
    const float* x_src     = (const float*)d_in[0];
    const float* x_tgt     = (const float*)d_in[1];
    const float* edge_attr = (const float*)d_in[2];
    const float* node_mask = (const float*)d_in[3];
    const float* edge_mask = (const float*)d_in[4];
    const int*   edge_idx  = (const int*)  d_in[5];
    const float* W1s = (const float*)d_in[6];
    const float* W1d = (const float*)d_in[7];
    const float* a1  = (const float*)d_in[8];
    const float* W2s = (const float*)d_in[9];
    const float* W2d = (const float*)d_in[10];
    const float* a2  = (const float*)d_in[11];
    const float* Wc  = (const float*)d_in[12];
    const float* bc  = (const float*)d_in[13];
    float* out = (float*)d_out;

    const int Ns = in_sizes[3];
    const int E  = in_sizes[4];
    const int Nt = in_sizes[1] / (NTYPES * FDIM);
    const int t  = NTYPES - 1;   // only the last edge type affects the output

    float *hs1, *hs2, *hd1, *hd2, *h1, *csrm, *pooled, *agg;
    int *cnt, *offs, *cursor, *csrs;
    cudaGetSymbolAddress((void**)&hs1, g_hs1);
    cudaGetSymbolAddress((void**)&hs2, g_hs2);
    cudaGetSymbolAddress((void**)&hd1, g_hd1);
    cudaGetSymbolAddress((void**)&hd2, g_hd2);
    cudaGetSymbolAddress((void**)&h1,  g_h1);
    cudaGetSymbolAddress((void**)&cnt,    g_cnt);
    cudaGetSymbolAddress((void**)&offs,   g_offs);
    cudaGetSymbolAddress((void**)&cursor, g_cursor);
    cudaGetSymbolAddress((void**)&csrs,   g_csrs);
    cudaGetSymbolAddress((void**)&csrm,   g_csrm);
    cudaGetSymbolAddress((void**)&pooled, g_pooled);
    cudaGetSymbolAddress((void**)&agg,    g_agg);

    const float* x_tgt5 = x_tgt + (size_t)t * Nt * FDIM;
    const float* W1s_t = W1s + (size_t)t * FDIM * HC;
    const float* W1d_t = W1d + (size_t)t * FDIM * HC;
    const float* W2s_t = W2s + (size_t)t * FDIM * HC;
    const float* W2d_t = W2d + (size_t)t * HC * HC;
    const float* a1_t = a1 + (size_t)t * HC;
    const float* a2_t = a2 + (size_t)t * HC;
    const int* src = edge_idx + (size_t)t * 2 * E;
    const int* dst = src + E;

    cudaMemsetAsync(cnt, 0, (size_t)Nt * sizeof(int));
    cudaMemsetAsync(pooled, 0, 256 * sizeof(float));

    const int eb = (E + 255) / 256;
    // CSR build (shared by both layers)
    hist_kernel<<<eb, 256>>>(dst, cnt, E);
    scan_kernel<<<1, 1024>>>(cnt, offs, cursor, Nt);
    permute_kernel<<<eb, 256>>>(src, dst, edge_mask, cursor, csrs, csrm, E);

    const int gmx = (Ns + BM - 1) / BM;
    // hs1|hs2 = (x_src*mask) @ [W1s | W2s]  (one pass over A, N=512)
    gemm_tf32_kernel<1><<<dim3(gmx, 4), 256>>>(x_src, W1s_t, W2s_t, hs1, hs2, node_mask, Ns, FDIM);
    // hd1 = (x_tgt5*mask) @ W1d
    gemm_tf32_kernel<1><<<dim3(gmx, 2), 256>>>(x_tgt5, W1d_t, nullptr, hd1, nullptr, node_mask, Nt, FDIM);

    const int ab = (Nt + 7) / 8;
    // layer 1: h1 = relu(normalized aggregation)
    agg_kernel<true, false><<<ab, 256>>>(hs1, hd1, a1_t, offs, csrs, csrm, h1, nullptr, Nt);

    // hd2 = h1 @ W2d
    gemm_tf32_kernel<0><<<dim3(gmx, 2), 256>>>(h1, W2d_t, nullptr, hd2, nullptr, nullptr, Nt, HC);

    // layer 2: aggregate + pool directly (never materialize h2)
    agg_kernel<false, true><<<ab, 256>>>(hs2, hd2, a2_t, offs, csrs, csrm, nullptr, pooled, Nt);

    // readout
    edgeattr_kernel<<<NTYPES, 256>>>(edge_attr, agg, E);
    final_kernel<<<1, 256>>>(pooled, agg, Wc, bc, out, Nt, E);
}